// round 16
// baseline (speedup 1.0000x reference)
#include <cuda_runtime.h>
#include <cuda_bf16.h>
#include <math.h>

#define SS 512
#define DD 768
#define PP 256
#define HH 12
#define DH 64
#define DFF 3072
#define M2 (2*PP)
#define EPS_LN 1e-5f
#define EPS_TRIP 1e-6f

// GEMM tile: BM=64, BN=64, BK=128, 128 threads (4 warps 2x2), warp tile 32x32, bf16 k16 MMA
#define SASB 136
#define ASZB (64 * SASB)
#define BSZB (64 * SASB)
#define NSTAGE 3
#define SMEM_BYTES (NSTAGE * (ASZB + BSZB) * 2)   // 104448 bytes

typedef __nv_bfloat16 bf16;

// ---------------- scratch ----------------
__device__ float g_sE[PP * DD];
__device__ float g_x[M2 * DD];
__device__ bf16  g_xbf[M2 * DD];
__device__ bf16  g_membf[M2 * DD];
__device__ bf16  g_qbf[M2 * DD];
__device__ bf16  g_Kbf[M2 * DD];
__device__ bf16  g_Vbf[M2 * DD];
__device__ bf16  g_obf[M2 * DD];
__device__ float g_ao[3 * M2 * DD];   // Wo split-K partials (3)
__device__ float g_h[M2 * DD];
__device__ bf16  g_hbf[M2 * DD];
__device__ bf16  g_f1bf[M2 * DFF];
__device__ float g_f2[4 * M2 * DD];   // W2 split-K partials (4)
// transposed bf16 weights [N][K]
__device__ bf16 g_Tq[DD * DD];
__device__ bf16 g_Tk[DD * DD];
__device__ bf16 g_Tv[DD * DD];
__device__ bf16 g_To[DD * DD];
__device__ bf16 g_T1[DFF * DD];
__device__ bf16 g_T2[DD * DFF];

// ---------------- helpers ----------------
__device__ __forceinline__ void gdc_wait() {
    asm volatile("griddepcontrol.wait;" ::: "memory");
}
__device__ __forceinline__ void gdc_launch() {
    asm volatile("griddepcontrol.launch_dependents;");
}

__device__ __forceinline__ void mma_bf16(float* c, const unsigned* a, unsigned b0, unsigned b1) {
    asm volatile(
        "mma.sync.aligned.m16n8k16.row.col.f32.bf16.bf16.f32 "
        "{%0,%1,%2,%3}, {%4,%5,%6,%7}, {%8,%9}, {%0,%1,%2,%3};"
        : "+f"(c[0]), "+f"(c[1]), "+f"(c[2]), "+f"(c[3])
        : "r"(a[0]), "r"(a[1]), "r"(a[2]), "r"(a[3]), "r"(b0), "r"(b1));
}

__device__ __forceinline__ void cp16(unsigned saddr, const void* gaddr) {
    asm volatile("cp.async.ca.shared.global [%0], [%1], 16;\n" :: "r"(saddr), "l"(gaddr));
}
__device__ __forceinline__ void cp_commit() {
    asm volatile("cp.async.commit_group;\n" ::);
}
__device__ __forceinline__ void cp_wait1() {
    asm volatile("cp.async.wait_group 1;\n" ::);
}

__device__ __forceinline__ float block_reduce_sum(float v, float* sh) {
    int lane = threadIdx.x & 31;
    int w = threadIdx.x >> 5;
    #pragma unroll
    for (int o = 16; o > 0; o >>= 1) v += __shfl_down_sync(0xffffffffu, v, o);
    __syncthreads();
    if (lane == 0) sh[w] = v;
    __syncthreads();
    int nw = blockDim.x >> 5;
    float r = (threadIdx.x < nw) ? sh[threadIdx.x] : 0.f;
    if (w == 0) {
        #pragma unroll
        for (int o = 16; o > 0; o >>= 1) r += __shfl_down_sync(0xffffffffu, r, o);
        if (lane == 0) sh[0] = r;
    }
    __syncthreads();
    return sh[0];
}

// ---------------- 32x32 transpose-convert tile, 256 threads ----------------
__device__ __forceinline__ void conv_tile256(const float* __restrict__ src, bf16* __restrict__ dst,
                                             int K, int N, int t0) {
    __shared__ float tile[32][33];
    int ntn = N / 32;
    int tk = t0 / ntn, tn = t0 % ntn;
    int tx = threadIdx.x & 31, ty = threadIdx.x >> 5;
    #pragma unroll
    for (int i = 0; i < 4; i++) {
        int k = tk * 32 + ty + i * 8;
        tile[ty + i * 8][tx] = src[(size_t)k * N + tn * 32 + tx];
    }
    __syncthreads();
    #pragma unroll
    for (int i = 0; i < 4; i++) {
        int n = tn * 32 + ty + i * 8;
        dst[(size_t)n * K + tk * 32 + tx] = __float2bfloat16_rn(tile[tx][ty + i * 8]);
    }
}

// ---------------- prep1: convert Tq/Tk/Tv (0..1727) + pool (1728..1983) ----------------
__global__ __launch_bounds__(256) void prep1_kernel(
    const float* __restrict__ Wq, const float* __restrict__ Wk, const float* __restrict__ Wv,
    const float* __restrict__ se, const int* __restrict__ sidx,
    const int* __restrict__ ss, const int* __restrict__ ps, const int* __restrict__ ns,
    float* __restrict__ out_zero) {
    int b = blockIdx.x;
    if (b < 1728) {
        int w = b / 576;
        const float* src = (w == 0) ? Wq : (w == 1) ? Wk : Wv;
        bf16* dst = (w == 0) ? g_Tq : (w == 1) ? g_Tk : g_Tv;
        conv_tile256(src, dst, DD, DD, b % 576);
    } else {
        int p = b - 1728;
        if (p == 0 && threadIdx.x == 0) out_zero[0] = 0.f;
        const float* base = se + (size_t)sidx[p] * SS * DD;
        int t = threadIdx.x;
        int s0 = ss[2 * p], s1 = ss[2 * p + 1];
        int p0 = ps[2 * p], p1 = ps[2 * p + 1];
        int n0 = ns[2 * p], n1 = ns[2 * p + 1];
        float inv_s = 1.0f / (float)(s1 - s0);
        float inv_p = 1.0f / (float)(p1 - p0);
        float inv_n = 1.0f / (float)(n1 - n0);
        #pragma unroll
        for (int i = 0; i < 3; i++) {
            int d = t + i * 256;
            float as = 0.f, ap = 0.f, an = 0.f;
            for (int r = s0; r < s1; r++) as += base[r * DD + d];
            for (int r = p0; r < p1; r++) ap += base[r * DD + d];
            for (int r = n0; r < n1; r++) an += base[r * DD + d];
            as *= inv_s; ap *= inv_p; an *= inv_n;
            g_sE[p * DD + d] = as;
            g_x[p * DD + d] = ap;
            g_x[(p + PP) * DD + d] = an;
            g_xbf[p * DD + d] = __float2bfloat16_rn(ap);
            g_xbf[(p + PP) * DD + d] = __float2bfloat16_rn(an);
            g_membf[p * 2 * DD + d] = __float2bfloat16_rn(base[d]);
            g_membf[p * 2 * DD + DD + d] = __float2bfloat16_rn(as);
        }
    }
    gdc_launch();
}

// ---------------- prep2: convert To (0..575), T1 (576..2879), T2 (2880..5183) ----------------
__global__ __launch_bounds__(256) void prep2_kernel(
    const float* __restrict__ Wo, const float* __restrict__ W1, const float* __restrict__ W2) {
    int b = blockIdx.x;
    if (b < 576) conv_tile256(Wo, g_To, DD, DD, b);
    else if (b < 2880) conv_tile256(W1, g_T1, DD, DFF, b - 576);
    else conv_tile256(W2, g_T2, DFF, DD, b - 2880);
}

// ---------------- bf16 GEMM body (BK=128, NSTAGE=3, one sync per iter) ----------------
// OUT: 0 = f32 store, 1 = bf16 store
template <int OUT, bool RELU, bool BIAS>
__device__ __forceinline__ void gemm_body(
    const bf16* __restrict__ A, const bf16* __restrict__ Bt,
    const float* __restrict__ bias, float* __restrict__ C, bf16* __restrict__ Cb,
    int K, int N, int kbeg, int kspan, int row0, int col0) {
    extern __shared__ bf16 smem[];
    bf16* sA = smem;
    bf16* sB = smem + NSTAGE * ASZB;

    int tid = threadIdx.x;
    int lane = tid & 31;
    int wid = tid >> 5;
    int wm = wid >> 1;
    int wn = wid & 1;
    int q = lane >> 2;
    int r4 = lane & 3;

    float acc[2][4][4];
    #pragma unroll
    for (int i = 0; i < 2; i++)
        #pragma unroll
        for (int j = 0; j < 4; j++)
            #pragma unroll
            for (int k = 0; k < 4; k++) acc[i][j][k] = 0.f;

    unsigned uA = (unsigned)__cvta_generic_to_shared(sA);
    unsigned uB = (unsigned)__cvta_generic_to_shared(sB);

    int niter = kspan / 128;

    auto issue = [&](int it) {
        if (it < niter) {
            int k0 = kbeg + it * 128;
            int s = it % NSTAGE;
            unsigned dA = uA + s * (ASZB * 2);
            unsigned dB = uB + s * (BSZB * 2);
            #pragma unroll
            for (int i = 0; i < 8; i++) {
                int idx = tid + i * 128;
                int r = idx >> 4;
                int c = (idx & 15) * 8;
                cp16(dA + (r * SASB + c) * 2, A + (size_t)(row0 + r) * K + k0 + c);
                cp16(dB + (r * SASB + c) * 2, Bt + (size_t)(col0 + r) * K + k0 + c);
            }
        }
        cp_commit();
    };

    auto compute = [&](int it) {
        int s = it % NSTAGE;
        const bf16* cA = sA + s * ASZB;
        const bf16* cB = sB + s * BSZB;
        #pragma unroll
        for (int ks = 0; ks < 8; ks++) {
            int kk = ks * 16;
            unsigned a[2][4];
            #pragma unroll
            for (int mt = 0; mt < 2; mt++) {
                int rr = wm * 32 + mt * 16 + q;
                a[mt][0] = *(const unsigned*)&cA[rr * SASB + kk + 2 * r4];
                a[mt][1] = *(const unsigned*)&cA[(rr + 8) * SASB + kk + 2 * r4];
                a[mt][2] = *(const unsigned*)&cA[rr * SASB + kk + 2 * r4 + 8];
                a[mt][3] = *(const unsigned*)&cA[(rr + 8) * SASB + kk + 2 * r4 + 8];
            }
            #pragma unroll
            for (int nt = 0; nt < 4; nt++) {
                int cc = wn * 32 + nt * 8 + q;
                unsigned b0 = *(const unsigned*)&cB[cc * SASB + kk + 2 * r4];
                unsigned b1 = *(const unsigned*)&cB[cc * SASB + kk + 2 * r4 + 8];
                mma_bf16(acc[0][nt], a[0], b0, b1);
                mma_bf16(acc[1][nt], a[1], b0, b1);
            }
        }
    };

    gdc_wait();          // PDL: block until producer's stores are visible
    issue(0);
    issue(1);
    // One sync per iteration: issue(it+2) overwrites stage (it-1)%3, which all
    // warps finished reading before this iteration's barrier (program order).
    for (int it = 0; it < niter; it++) {
        cp_wait1();
        __syncthreads();
        issue(it + 2);
        compute(it);
    }

    #pragma unroll
    for (int mt = 0; mt < 2; mt++) {
        int rr = row0 + wm * 32 + mt * 16 + q;
        #pragma unroll
        for (int nt = 0; nt < 4; nt++) {
            int cc = col0 + wn * 32 + nt * 8 + 2 * r4;
            float b0 = 0.f, b1 = 0.f;
            if (BIAS) { b0 = bias[cc]; b1 = bias[cc + 1]; }
            float v0 = acc[mt][nt][0] + b0;
            float v1 = acc[mt][nt][1] + b1;
            float v2 = acc[mt][nt][2] + b0;
            float v3 = acc[mt][nt][3] + b1;
            if (RELU) {
                v0 = fmaxf(v0, 0.f); v1 = fmaxf(v1, 0.f);
                v2 = fmaxf(v2, 0.f); v3 = fmaxf(v3, 0.f);
            }
            if (OUT == 0) {
                *(float2*)&C[(size_t)rr * N + cc] = make_float2(v0, v1);
                *(float2*)&C[(size_t)(rr + 8) * N + cc] = make_float2(v2, v3);
            } else {
                __nv_bfloat162 w0, w1;
                w0.x = __float2bfloat16_rn(v0); w0.y = __float2bfloat16_rn(v1);
                w1.x = __float2bfloat16_rn(v2); w1.y = __float2bfloat16_rn(v3);
                *(__nv_bfloat162*)&Cb[(size_t)rr * N + cc] = w0;
                *(__nv_bfloat162*)&Cb[(size_t)(rr + 8) * N + cc] = w1;
            }
        }
    }
    gdc_launch();        // PDL: all stores issued -> dependents may launch
}

// ---------------- QKV GEMM (grid.z = 3: 0=K 1=V 2=Q), bf16 out, bias epilogue ----------------
__global__ __launch_bounds__(128) void tgemm_qkv(
    const float* __restrict__ bq, const float* __restrict__ bk, const float* __restrict__ bv) {
    int z = blockIdx.z;
    const bf16* A = (z == 2) ? g_xbf : g_membf;
    const bf16* B = (z == 0) ? g_Tk : ((z == 1) ? g_Tv : g_Tq);
    const float* bias = (z == 0) ? bk : ((z == 1) ? bv : bq);
    bf16* Cb = (z == 0) ? g_Kbf : ((z == 1) ? g_Vbf : g_qbf);
    gemm_body<1, false, true>(A, B, bias, nullptr, Cb, DD, DD, 0, DD,
                              blockIdx.y * 64, blockIdx.x * 64);
}

// ---------------- split-K GEMM -> partial buffers ----------------
template <int SPLITK>
__global__ __launch_bounds__(128) void tgemm_split(
    const bf16* __restrict__ A, const bf16* __restrict__ Bt,
    float* __restrict__ C, int M, int K, int N) {
    int z = blockIdx.z;
    int kspan = K / SPLITK;
    float* Cz = C + (size_t)z * M * N;
    gemm_body<0, false, false>(A, Bt, nullptr, Cz, nullptr, K, N, z * kspan, kspan,
                               blockIdx.y * 64, blockIdx.x * 64);
}

// ---------------- W1 GEMM (bias + ReLU + bf16 out) ----------------
__global__ __launch_bounds__(128) void tgemm_w1(const float* __restrict__ b1) {
    gemm_body<1, true, true>(g_hbf, g_T1, b1, nullptr, g_f1bf, DD, DFF, 0, DD,
                             blockIdx.y * 64, blockIdx.x * 64);
}

// ---------------- 2-slot attention: warp per (row, head), bf16 in, shfl-only ----------------
__global__ __launch_bounds__(256) void attn_kernel(
    const bf16* __restrict__ q, const bf16* __restrict__ Kb,
    const bf16* __restrict__ Vb, bf16* __restrict__ obf) {
    int wid = threadIdx.x >> 5;
    int lane = threadIdx.x & 31;
    int wg = blockIdx.x * 8 + wid;
    int r = wg / HH;
    int h = wg % HH;
    int p = r & (PP - 1);
    int hd = h * DH + lane * 2;
    size_t qoff = (size_t)r * DD + hd;
    size_t k0off = (size_t)p * 2 * DD + hd;

    gdc_wait();

    float2 qv = __bfloat1622float2(*(const __nv_bfloat162*)&q[qoff]);
    float2 k0 = __bfloat1622float2(*(const __nv_bfloat162*)&Kb[k0off]);
    float2 k1 = __bfloat1622float2(*(const __nv_bfloat162*)&Kb[k0off + DD]);
    float2 v0 = __bfloat1622float2(*(const __nv_bfloat162*)&Vb[k0off]);
    float2 v1 = __bfloat1622float2(*(const __nv_bfloat162*)&Vb[k0off + DD]);

    float s0 = qv.x * k0.x + qv.y * k0.y;
    float s1 = qv.x * k1.x + qv.y * k1.y;
    #pragma unroll
    for (int off = 16; off > 0; off >>= 1) {
        s0 += __shfl_xor_sync(0xffffffffu, s0, off);
        s1 += __shfl_xor_sync(0xffffffffu, s1, off);
    }
    s0 *= 0.125f;
    s1 *= 0.125f;
    float m = fmaxf(s0, s1);
    float e0 = expf(s0 - m), e1 = expf(s1 - m);
    float inv = 1.f / (e0 + e1);
    float a0 = e0 * inv, a1 = e1 * inv;

    __nv_bfloat162 o;
    o.x = __float2bfloat16_rn(a0 * v0.x + a1 * v1.x);
    o.y = __float2bfloat16_rn(a0 * v0.y + a1 * v1.y);
    *(__nv_bfloat162*)&obf[qoff] = o;
    gdc_launch();
}

// ---------------- residual + 3 partials + bias + LayerNorm (f32 + bf16 out) ----------------
__global__ void add_ln_kernel(const float* __restrict__ x, const float* __restrict__ parts,
                              const float* __restrict__ bias,
                              const float* __restrict__ g, const float* __restrict__ b,
                              float* __restrict__ out, bf16* __restrict__ outbf) {
    int p = blockIdx.x;
    int t = threadIdx.x;
    __shared__ float sh[8];
    float v[3];
    float s = 0.f, s2 = 0.f;
    gdc_wait();
    #pragma unroll
    for (int i = 0; i < 3; i++) {
        int d = t + i * 256;
        float acc = x[(size_t)p * DD + d] + bias[d];
        #pragma unroll
        for (int k = 0; k < 3; k++)
            acc += parts[(size_t)k * M2 * DD + (size_t)p * DD + d];
        v[i] = acc;
        s += acc;
        s2 += acc * acc;
    }
    float sum = block_reduce_sum(s, sh);
    float sumsq = block_reduce_sum(s2, sh);
    float mean = sum * (1.0f / DD);
    float var = sumsq * (1.0f / DD) - mean * mean;
    float rstd = rsqrtf(var + EPS_LN);
    #pragma unroll
    for (int i = 0; i < 3; i++) {
        int d = t + i * 256;
        float o = (v[i] - mean) * rstd * g[d] + b[d];
        out[(size_t)p * DD + d] = o;
        outbf[(size_t)p * DD + d] = __float2bfloat16_rn(o);
    }
    gdc_launch();
}

// ---------------- fused: 2nd add+LN (4 partials) + triplet loss + mean (atomic) ----------------
__global__ void add_ln_loss_kernel(const float* __restrict__ hb, const float* __restrict__ parts,
                                   const float* __restrict__ bias,
                                   const float* __restrict__ g, const float* __restrict__ b,
                                   const float* __restrict__ sE, float* __restrict__ out) {
    int p = blockIdx.x;
    int t = threadIdx.x;
    __shared__ float sh[8];
    float vp[3], vn[3];
    float sp = 0.f, sp2 = 0.f, sn = 0.f, sn2 = 0.f;
    gdc_wait();
    #pragma unroll
    for (int i = 0; i < 3; i++) {
        int d = t + i * 256;
        float ap = hb[(size_t)p * DD + d] + bias[d];
        float an = hb[(size_t)(p + PP) * DD + d] + bias[d];
        #pragma unroll
        for (int k = 0; k < 4; k++) {
            ap += parts[(size_t)k * M2 * DD + (size_t)p * DD + d];
            an += parts[(size_t)k * M2 * DD + (size_t)(p + PP) * DD + d];
        }
        vp[i] = ap; vn[i] = an;
        sp += ap; sp2 += ap * ap;
        sn += an; sn2 += an * an;
    }
    float sump = block_reduce_sum(sp, sh);
    float sumsqp = block_reduce_sum(sp2, sh);
    float sumn = block_reduce_sum(sn, sh);
    float sumsqn = block_reduce_sum(sn2, sh);
    float meanp = sump * (1.0f / DD);
    float rstdp = rsqrtf(sumsqp * (1.0f / DD) - meanp * meanp + EPS_LN);
    float meann = sumn * (1.0f / DD);
    float rstdn = rsqrtf(sumsqn * (1.0f / DD) - meann * meann + EPS_LN);
    float dp = 0.f, dn = 0.f;
    #pragma unroll
    for (int i = 0; i < 3; i++) {
        int d = t + i * 256;
        float attp = (vp[i] - meanp) * rstdp * g[d] + b[d];
        float attn = (vn[i] - meann) * rstdn * g[d] + b[d];
        float e = sE[(size_t)p * DD + d];
        float a = e - attp + EPS_TRIP;
        float c = e - attn + EPS_TRIP;
        dp += a * a;
        dn += c * c;
    }
    float DP = block_reduce_sum(dp, sh);
    float DN = block_reduce_sum(dn, sh);
    if (t == 0) {
        float hinge = fmaxf(sqrtf(DP) - sqrtf(DN) + 1.0f, 0.f);
        atomicAdd(out, hinge * (1.0f / PP));
    }
}

// ---------------- host launch ----------------
extern "C" void kernel_launch(void* const* d_in, const int* in_sizes, int n_in,
                              void* d_out, int out_size) {
    const float* sent = (const float*)d_in[0];
    const int* sidx = (const int*)d_in[1];
    const int* ss = (const int*)d_in[2];
    const int* ps = (const int*)d_in[3];
    const int* ns = (const int*)d_in[4];
    const float* Wq = (const float*)d_in[5];
    const float* bq = (const float*)d_in[6];
    const float* Wk = (const float*)d_in[7];
    const float* bk = (const float*)d_in[8];
    const float* Wv = (const float*)d_in[9];
    const float* bv = (const float*)d_in[10];
    const float* Wo = (const float*)d_in[11];
    const float* bo = (const float*)d_in[12];
    const float* l1g = (const float*)d_in[13];
    const float* l1b = (const float*)d_in[14];
    const float* l2g = (const float*)d_in[15];
    const float* l2b = (const float*)d_in[16];
    const float* W1 = (const float*)d_in[17];
    const float* b1 = (const float*)d_in[18];
    const float* W2 = (const float*)d_in[19];
    const float* b2 = (const float*)d_in[20];
    float* out = (float*)d_out;

    float *sE, *xb, *ao, *hb, *f2;
    bf16 *qbf, *Kbf, *Vbf, *obf, *hbf, *f1bf, *To, *T2;
    cudaGetSymbolAddress((void**)&sE, g_sE);
    cudaGetSymbolAddress((void**)&xb, g_x);
    cudaGetSymbolAddress((void**)&qbf, g_qbf);
    cudaGetSymbolAddress((void**)&Kbf, g_Kbf);
    cudaGetSymbolAddress((void**)&Vbf, g_Vbf);
    cudaGetSymbolAddress((void**)&ao, g_ao);
    cudaGetSymbolAddress((void**)&hb, g_h);
    cudaGetSymbolAddress((void**)&f2, g_f2);
    cudaGetSymbolAddress((void**)&obf, g_obf);
    cudaGetSymbolAddress((void**)&hbf, g_hbf);
    cudaGetSymbolAddress((void**)&f1bf, g_f1bf);
    cudaGetSymbolAddress((void**)&To, g_To);
    cudaGetSymbolAddress((void**)&T2, g_T2);

    cudaFuncSetAttribute(tgemm_qkv, cudaFuncAttributeMaxDynamicSharedMemorySize, SMEM_BYTES);
    cudaFuncSetAttribute(tgemm_split<3>, cudaFuncAttributeMaxDynamicSharedMemorySize, SMEM_BYTES);
    cudaFuncSetAttribute(tgemm_split<4>, cudaFuncAttributeMaxDynamicSharedMemorySize, SMEM_BYTES);
    cudaFuncSetAttribute(tgemm_w1, cudaFuncAttributeMaxDynamicSharedMemorySize, SMEM_BYTES);

    // one-time side-stream + events
    static cudaStream_t s2 = nullptr;
    static cudaEvent_t evFork = nullptr, evJoin = nullptr;
    if (s2 == nullptr) {
        cudaStreamCreateWithFlags(&s2, cudaStreamNonBlocking);
        cudaEventCreateWithFlags(&evFork, cudaEventDisableTiming);
        cudaEventCreateWithFlags(&evJoin, cudaEventDisableTiming);
    }

    // PDL launch attribute
    cudaLaunchAttribute pa[1];
    pa[0].id = cudaLaunchAttributeProgrammaticStreamSerialization;
    pa[0].val.programmaticStreamSerializationAllowed = 1;
    auto pdl = [&](dim3 g, dim3 b, size_t sm) {
        cudaLaunchConfig_t c{};
        c.gridDim = g; c.blockDim = b; c.dynamicSmemBytes = sm;
        c.stream = 0; c.attrs = pa; c.numAttrs = 1;
        return c;
    };

    // fork: To/T1/T2 conversion runs concurrently with prep1+QKV+attn
    cudaEventRecord(evFork, 0);
    cudaStreamWaitEvent(s2, evFork, 0);
    prep2_kernel<<<5184, 256, 0, s2>>>(Wo, W1, W2);
    cudaEventRecord(evJoin, s2);

    prep1_kernel<<<1984, 256>>>(Wq, Wk, Wv, sent, sidx, ss, ps, ns, out);

    dim3 gQKV(12, 8, 3);   // 288 blocks, 6 iters
    dim3 gWo(12, 8, 3);    // 288 blocks, 2 iters (split-3)
    dim3 gW1(48, 8, 1);    // 384 blocks, 6 iters
    dim3 gW2(12, 8, 4);    // 384 blocks, 6 iters

    {   // QKV: PDL after prep1
        cudaLaunchConfig_t c = pdl(gQKV, dim3(128), SMEM_BYTES);
        cudaLaunchKernelEx(&c, tgemm_qkv, bq, bk, bv);
    }
    {   // attn: PDL after QKV
        cudaLaunchConfig_t c = pdl(dim3(M2 * HH / 8), dim3(256), 0);
        cudaLaunchKernelEx(&c, attn_kernel,
                           (const bf16*)qbf, (const bf16*)Kbf, (const bf16*)Vbf, obf);
    }

    // join: Wo/W1/W2 need the converted weights (Wo launched WITHOUT PDL: event edge)
    cudaStreamWaitEvent(0, evJoin, 0);
    tgemm_split<3><<<gWo, 128, SMEM_BYTES>>>((const bf16*)obf, (const bf16*)To, ao, M2, DD, DD);

    {   // add_ln: PDL after Wo
        cudaLaunchConfig_t c = pdl(dim3(M2), dim3(256), 0);
        cudaLaunchKernelEx(&c, add_ln_kernel,
                           (const float*)xb, (const float*)ao, bo, l1g, l1b, hb, hbf);
    }
    {   // W1: PDL after add_ln
        cudaLaunchConfig_t c = pdl(gW1, dim3(128), SMEM_BYTES);
        cudaLaunchKernelEx(&c, tgemm_w1, b1);
    }
    {   // W2: PDL after W1
        cudaLaunchConfig_t c = pdl(gW2, dim3(128), SMEM_BYTES);
        cudaLaunchKernelEx(&c, tgemm_split<4>,
                           (const bf16*)f1bf, (const bf16*)T2, f2, M2, DFF, DD);
    }
    {   // loss: PDL after W2
        cudaLaunchConfig_t c = pdl(dim3(PP), dim3(256), 0);
        cudaLaunchKernelEx(&c, add_ln_loss_kernel,
                           (const float*)hb, (const float*)f2, b2, l2g, l2b,
                           (const float*)sE, out);
    }
}

// round 17
// speedup vs baseline: 1.0797x; 1.0797x over previous
#include <cuda_runtime.h>
#include <cuda_bf16.h>
#include <math.h>

#define SS 512
#define DD 768
#define PP 256
#define HH 12
#define DH 64
#define DFF 3072
#define M2 (2*PP)
#define EPS_LN 1e-5f
#define EPS_TRIP 1e-6f

// GEMM tile: BM=64, BN=64, BK=128, 128 threads (4 warps 2x2), warp tile 32x32, bf16 k16 MMA
#define SASB 136
#define ASZB (64 * SASB)
#define BSZB (64 * SASB)
#define NSTAGE 2
#define SMEM_BYTES (NSTAGE * (ASZB + BSZB) * 2)   // 69632 bytes

typedef __nv_bfloat16 bf16;

// ---------------- scratch ----------------
__device__ float g_sE[PP * DD];
__device__ float g_x[M2 * DD];
__device__ bf16  g_xbf[M2 * DD];
__device__ bf16  g_membf[M2 * DD];
__device__ float g_q[M2 * DD];
__device__ float g_K[M2 * DD];
__device__ float g_V[M2 * DD];
__device__ bf16  g_obf[M2 * DD];
__device__ float g_ao[3 * M2 * DD];   // Wo split-K partials (3)
__device__ float g_h[M2 * DD];
__device__ bf16  g_hbf[M2 * DD];
__device__ bf16  g_f1bf[M2 * DFF];
__device__ float g_f2[4 * M2 * DD];   // W2 split-K partials (4)
// transposed bf16 weights [N][K]
__device__ bf16 g_Tq[DD * DD];
__device__ bf16 g_Tk[DD * DD];
__device__ bf16 g_Tv[DD * DD];
__device__ bf16 g_To[DD * DD];
__device__ bf16 g_T1[DFF * DD];
__device__ bf16 g_T2[DD * DFF];

// ---------------- helpers ----------------
__device__ __forceinline__ void gdc_wait() {
    asm volatile("griddepcontrol.wait;" ::: "memory");
}
__device__ __forceinline__ void gdc_launch() {
    asm volatile("griddepcontrol.launch_dependents;");
}

__device__ __forceinline__ void mma_bf16(float* c, const unsigned* a, unsigned b0, unsigned b1) {
    asm volatile(
        "mma.sync.aligned.m16n8k16.row.col.f32.bf16.bf16.f32 "
        "{%0,%1,%2,%3}, {%4,%5,%6,%7}, {%8,%9}, {%0,%1,%2,%3};"
        : "+f"(c[0]), "+f"(c[1]), "+f"(c[2]), "+f"(c[3])
        : "r"(a[0]), "r"(a[1]), "r"(a[2]), "r"(a[3]), "r"(b0), "r"(b1));
}

__device__ __forceinline__ void cp16(unsigned saddr, const void* gaddr) {
    asm volatile("cp.async.ca.shared.global [%0], [%1], 16;\n" :: "r"(saddr), "l"(gaddr));
}
__device__ __forceinline__ void cp_commit() {
    asm volatile("cp.async.commit_group;\n" ::);
}
__device__ __forceinline__ void cp_wait1() {
    asm volatile("cp.async.wait_group 1;\n" ::);
}

__device__ __forceinline__ float block_reduce_sum(float v, float* sh) {
    int lane = threadIdx.x & 31;
    int w = threadIdx.x >> 5;
    #pragma unroll
    for (int o = 16; o > 0; o >>= 1) v += __shfl_down_sync(0xffffffffu, v, o);
    __syncthreads();
    if (lane == 0) sh[w] = v;
    __syncthreads();
    int nw = blockDim.x >> 5;
    float r = (threadIdx.x < nw) ? sh[threadIdx.x] : 0.f;
    if (w == 0) {
        #pragma unroll
        for (int o = 16; o > 0; o >>= 1) r += __shfl_down_sync(0xffffffffu, r, o);
        if (lane == 0) sh[0] = r;
    }
    __syncthreads();
    return sh[0];
}

// ---------------- 32x32 transpose-convert tile, 256 threads ----------------
__device__ __forceinline__ void conv_tile256(const float* __restrict__ src, bf16* __restrict__ dst,
                                             int K, int N, int t0) {
    __shared__ float tile[32][33];
    int ntn = N / 32;
    int tk = t0 / ntn, tn = t0 % ntn;
    int tx = threadIdx.x & 31, ty = threadIdx.x >> 5;
    #pragma unroll
    for (int i = 0; i < 4; i++) {
        int k = tk * 32 + ty + i * 8;
        tile[ty + i * 8][tx] = src[(size_t)k * N + tn * 32 + tx];
    }
    __syncthreads();
    #pragma unroll
    for (int i = 0; i < 4; i++) {
        int n = tn * 32 + ty + i * 8;
        dst[(size_t)n * K + tk * 32 + tx] = __float2bfloat16_rn(tile[tx][ty + i * 8]);
    }
}

// ---------------- prep1: convert Tq/Tk/Tv (0..1727) + pool (1728..1983) ----------------
__global__ __launch_bounds__(256) void prep1_kernel(
    const float* __restrict__ Wq, const float* __restrict__ Wk, const float* __restrict__ Wv,
    const float* __restrict__ se, const int* __restrict__ sidx,
    const int* __restrict__ ss, const int* __restrict__ ps, const int* __restrict__ ns,
    float* __restrict__ out_zero) {
    int b = blockIdx.x;
    if (b < 1728) {
        int w = b / 576;
        const float* src = (w == 0) ? Wq : (w == 1) ? Wk : Wv;
        bf16* dst = (w == 0) ? g_Tq : (w == 1) ? g_Tk : g_Tv;
        conv_tile256(src, dst, DD, DD, b % 576);
    } else {
        int p = b - 1728;
        if (p == 0 && threadIdx.x == 0) out_zero[0] = 0.f;
        const float* base = se + (size_t)sidx[p] * SS * DD;
        int t = threadIdx.x;
        int s0 = ss[2 * p], s1 = ss[2 * p + 1];
        int p0 = ps[2 * p], p1 = ps[2 * p + 1];
        int n0 = ns[2 * p], n1 = ns[2 * p + 1];
        float inv_s = 1.0f / (float)(s1 - s0);
        float inv_p = 1.0f / (float)(p1 - p0);
        float inv_n = 1.0f / (float)(n1 - n0);
        #pragma unroll
        for (int i = 0; i < 3; i++) {
            int d = t + i * 256;
            float as = 0.f, ap = 0.f, an = 0.f;
            for (int r = s0; r < s1; r++) as += base[r * DD + d];
            for (int r = p0; r < p1; r++) ap += base[r * DD + d];
            for (int r = n0; r < n1; r++) an += base[r * DD + d];
            as *= inv_s; ap *= inv_p; an *= inv_n;
            g_sE[p * DD + d] = as;
            g_x[p * DD + d] = ap;
            g_x[(p + PP) * DD + d] = an;
            g_xbf[p * DD + d] = __float2bfloat16_rn(ap);
            g_xbf[(p + PP) * DD + d] = __float2bfloat16_rn(an);
            g_membf[p * 2 * DD + d] = __float2bfloat16_rn(base[d]);
            g_membf[p * 2 * DD + DD + d] = __float2bfloat16_rn(as);
        }
    }
    gdc_launch();
}

// ---------------- prep2: convert To (0..575), T1 (576..2879), T2 (2880..5183) ----------------
__global__ __launch_bounds__(256) void prep2_kernel(
    const float* __restrict__ Wo, const float* __restrict__ W1, const float* __restrict__ W2) {
    int b = blockIdx.x;
    if (b < 576) conv_tile256(Wo, g_To, DD, DD, b);
    else if (b < 2880) conv_tile256(W1, g_T1, DD, DFF, b - 576);
    else conv_tile256(W2, g_T2, DFF, DD, b - 2880);
}

// ---------------- bf16 GEMM body (BK=128, NSTAGE=2, dynamic smem) ----------------
// OUT: 0 = f32 store, 1 = bf16 store
template <int OUT, bool RELU, bool BIAS>
__device__ __forceinline__ void gemm_body(
    const bf16* __restrict__ A, const bf16* __restrict__ Bt,
    const float* __restrict__ bias, float* __restrict__ C, bf16* __restrict__ Cb,
    int K, int N, int kbeg, int kspan, int row0, int col0) {
    extern __shared__ bf16 smem[];
    bf16* sA = smem;
    bf16* sB = smem + NSTAGE * ASZB;

    int tid = threadIdx.x;
    int lane = tid & 31;
    int wid = tid >> 5;
    int wm = wid >> 1;
    int wn = wid & 1;
    int q = lane >> 2;
    int r4 = lane & 3;

    float acc[2][4][4];
    #pragma unroll
    for (int i = 0; i < 2; i++)
        #pragma unroll
        for (int j = 0; j < 4; j++)
            #pragma unroll
            for (int k = 0; k < 4; k++) acc[i][j][k] = 0.f;

    unsigned uA = (unsigned)__cvta_generic_to_shared(sA);
    unsigned uB = (unsigned)__cvta_generic_to_shared(sB);

    int niter = kspan / 128;

    auto issue = [&](int it) {
        if (it < niter) {
            int k0 = kbeg + it * 128;
            int s = it & 1;
            unsigned dA = uA + s * (ASZB * 2);
            unsigned dB = uB + s * (BSZB * 2);
            #pragma unroll
            for (int i = 0; i < 8; i++) {
                int idx = tid + i * 128;
                int r = idx >> 4;
                int c = (idx & 15) * 8;
                cp16(dA + (r * SASB + c) * 2, A + (size_t)(row0 + r) * K + k0 + c);
                cp16(dB + (r * SASB + c) * 2, Bt + (size_t)(col0 + r) * K + k0 + c);
            }
        }
        cp_commit();
    };

    auto compute = [&](int it) {
        int s = it & 1;
        const bf16* cA = sA + s * ASZB;
        const bf16* cB = sB + s * BSZB;
        #pragma unroll
        for (int ks = 0; ks < 8; ks++) {
            int kk = ks * 16;
            unsigned a[2][4];
            #pragma unroll
            for (int mt = 0; mt < 2; mt++) {
                int rr = wm * 32 + mt * 16 + q;
                a[mt][0] = *(const unsigned*)&cA[rr * SASB + kk + 2 * r4];
                a[mt][1] = *(const unsigned*)&cA[(rr + 8) * SASB + kk + 2 * r4];
                a[mt][2] = *(const unsigned*)&cA[rr * SASB + kk + 2 * r4 + 8];
                a[mt][3] = *(const unsigned*)&cA[(rr + 8) * SASB + kk + 2 * r4 + 8];
            }
            #pragma unroll
            for (int nt = 0; nt < 4; nt++) {
                int cc = wn * 32 + nt * 8 + q;
                unsigned b0 = *(const unsigned*)&cB[cc * SASB + kk + 2 * r4];
                unsigned b1 = *(const unsigned*)&cB[cc * SASB + kk + 2 * r4 + 8];
                mma_bf16(acc[0][nt], a[0], b0, b1);
                mma_bf16(acc[1][nt], a[1], b0, b1);
            }
        }
    };

    gdc_wait();          // PDL: block until producer's stores are visible
    issue(0);
    issue(1);
    for (int it = 0; it < niter; it++) {
        cp_wait1();
        __syncthreads();
        compute(it);
        __syncthreads();
        issue(it + 2);
    }

    #pragma unroll
    for (int mt = 0; mt < 2; mt++) {
        int rr = row0 + wm * 32 + mt * 16 + q;
        #pragma unroll
        for (int nt = 0; nt < 4; nt++) {
            int cc = col0 + wn * 32 + nt * 8 + 2 * r4;
            float b0 = 0.f, b1 = 0.f;
            if (BIAS) { b0 = bias[cc]; b1 = bias[cc + 1]; }
            float v0 = acc[mt][nt][0] + b0;
            float v1 = acc[mt][nt][1] + b1;
            float v2 = acc[mt][nt][2] + b0;
            float v3 = acc[mt][nt][3] + b1;
            if (RELU) {
                v0 = fmaxf(v0, 0.f); v1 = fmaxf(v1, 0.f);
                v2 = fmaxf(v2, 0.f); v3 = fmaxf(v3, 0.f);
            }
            if (OUT == 0) {
                *(float2*)&C[(size_t)rr * N + cc] = make_float2(v0, v1);
                *(float2*)&C[(size_t)(rr + 8) * N + cc] = make_float2(v2, v3);
            } else {
                __nv_bfloat162 w0, w1;
                w0.x = __float2bfloat16_rn(v0); w0.y = __float2bfloat16_rn(v1);
                w1.x = __float2bfloat16_rn(v2); w1.y = __float2bfloat16_rn(v3);
                *(__nv_bfloat162*)&Cb[(size_t)rr * N + cc] = w0;
                *(__nv_bfloat162*)&Cb[(size_t)(rr + 8) * N + cc] = w1;
            }
        }
    }
    gdc_launch();        // PDL: all stores issued -> dependents may launch
}

// ---------------- QKV GEMM (grid.z = 3: 0=K 1=V 2=Q), unsplit, bias epilogue ----------------
__global__ __launch_bounds__(128) void tgemm_qkv(
    const float* __restrict__ bq, const float* __restrict__ bk, const float* __restrict__ bv) {
    int z = blockIdx.z;
    const bf16* A = (z == 2) ? g_xbf : g_membf;
    const bf16* B = (z == 0) ? g_Tk : ((z == 1) ? g_Tv : g_Tq);
    const float* bias = (z == 0) ? bk : ((z == 1) ? bv : bq);
    float* C = (z == 0) ? g_K : ((z == 1) ? g_V : g_q);
    gemm_body<0, false, true>(A, B, bias, C, nullptr, DD, DD, 0, DD,
                              blockIdx.y * 64, blockIdx.x * 64);
}

// ---------------- split-K GEMM -> partial buffers ----------------
template <int SPLITK>
__global__ __launch_bounds__(128) void tgemm_split(
    const bf16* __restrict__ A, const bf16* __restrict__ Bt,
    float* __restrict__ C, int M, int K, int N) {
    int z = blockIdx.z;
    int kspan = K / SPLITK;
    float* Cz = C + (size_t)z * M * N;
    gemm_body<0, false, false>(A, Bt, nullptr, Cz, nullptr, K, N, z * kspan, kspan,
                               blockIdx.y * 64, blockIdx.x * 64);
}

// ---------------- W1 GEMM (bias + ReLU + bf16 out) ----------------
__global__ __launch_bounds__(128) void tgemm_w1(const float* __restrict__ b1) {
    gemm_body<1, true, true>(g_hbf, g_T1, b1, nullptr, g_f1bf, DD, DFF, 0, DD,
                             blockIdx.y * 64, blockIdx.x * 64);
}

// ---------------- 2-slot attention: warp per (row, head), shfl-only ----------------
__global__ __launch_bounds__(256) void attn_kernel(
    const float* __restrict__ q, const float* __restrict__ Kb,
    const float* __restrict__ Vb, bf16* __restrict__ obf) {
    int wid = threadIdx.x >> 5;
    int lane = threadIdx.x & 31;
    int wg = blockIdx.x * 8 + wid;
    int r = wg / HH;
    int h = wg % HH;
    int p = r & (PP - 1);
    int hd = h * DH + lane * 2;
    size_t qoff = (size_t)r * DD + hd;
    size_t k0off = (size_t)p * 2 * DD + hd;

    gdc_wait();

    float2 qv = *(const float2*)&q[qoff];
    float2 k0 = *(const float2*)&Kb[k0off];
    float2 k1 = *(const float2*)&Kb[k0off + DD];
    float2 v0 = *(const float2*)&Vb[k0off];
    float2 v1 = *(const float2*)&Vb[k0off + DD];

    float s0 = qv.x * k0.x + qv.y * k0.y;
    float s1 = qv.x * k1.x + qv.y * k1.y;
    #pragma unroll
    for (int off = 16; off > 0; off >>= 1) {
        s0 += __shfl_xor_sync(0xffffffffu, s0, off);
        s1 += __shfl_xor_sync(0xffffffffu, s1, off);
    }
    s0 *= 0.125f;
    s1 *= 0.125f;
    float m = fmaxf(s0, s1);
    float e0 = expf(s0 - m), e1 = expf(s1 - m);
    float inv = 1.f / (e0 + e1);
    float a0 = e0 * inv, a1 = e1 * inv;

    __nv_bfloat162 o;
    o.x = __float2bfloat16_rn(a0 * v0.x + a1 * v1.x);
    o.y = __float2bfloat16_rn(a0 * v0.y + a1 * v1.y);
    *(__nv_bfloat162*)&obf[qoff] = o;
    gdc_launch();
}

// ---------------- residual + 3 partials + bias + LayerNorm (f32 + bf16 out) ----------------
__global__ void add_ln_kernel(const float* __restrict__ x, const float* __restrict__ parts,
                              const float* __restrict__ bias,
                              const float* __restrict__ g, const float* __restrict__ b,
                              float* __restrict__ out, bf16* __restrict__ outbf) {
    int p = blockIdx.x;
    int t = threadIdx.x;
    __shared__ float sh[8];
    float v[3];
    float s = 0.f, s2 = 0.f;
    gdc_wait();
    #pragma unroll
    for (int i = 0; i < 3; i++) {
        int d = t + i * 256;
        float acc = x[(size_t)p * DD + d] + bias[d];
        #pragma unroll
        for (int k = 0; k < 3; k++)
            acc += parts[(size_t)k * M2 * DD + (size_t)p * DD + d];
        v[i] = acc;
        s += acc;
        s2 += acc * acc;
    }
    float sum = block_reduce_sum(s, sh);
    float sumsq = block_reduce_sum(s2, sh);
    float mean = sum * (1.0f / DD);
    float var = sumsq * (1.0f / DD) - mean * mean;
    float rstd = rsqrtf(var + EPS_LN);
    #pragma unroll
    for (int i = 0; i < 3; i++) {
        int d = t + i * 256;
        float o = (v[i] - mean) * rstd * g[d] + b[d];
        out[(size_t)p * DD + d] = o;
        outbf[(size_t)p * DD + d] = __float2bfloat16_rn(o);
    }
    gdc_launch();
}

// ---------------- fused: 2nd add+LN (4 partials) + triplet loss + mean (atomic) ----------------
__global__ void add_ln_loss_kernel(const float* __restrict__ hb, const float* __restrict__ parts,
                                   const float* __restrict__ bias,
                                   const float* __restrict__ g, const float* __restrict__ b,
                                   const float* __restrict__ sE, float* __restrict__ out) {
    int p = blockIdx.x;
    int t = threadIdx.x;
    __shared__ float sh[8];
    float vp[3], vn[3];
    float sp = 0.f, sp2 = 0.f, sn = 0.f, sn2 = 0.f;
    gdc_wait();
    #pragma unroll
    for (int i = 0; i < 3; i++) {
        int d = t + i * 256;
        float ap = hb[(size_t)p * DD + d] + bias[d];
        float an = hb[(size_t)(p + PP) * DD + d] + bias[d];
        #pragma unroll
        for (int k = 0; k < 4; k++) {
            ap += parts[(size_t)k * M2 * DD + (size_t)p * DD + d];
            an += parts[(size_t)k * M2 * DD + (size_t)(p + PP) * DD + d];
        }
        vp[i] = ap; vn[i] = an;
        sp += ap; sp2 += ap * ap;
        sn += an; sn2 += an * an;
    }
    float sump = block_reduce_sum(sp, sh);
    float sumsqp = block_reduce_sum(sp2, sh);
    float sumn = block_reduce_sum(sn, sh);
    float sumsqn = block_reduce_sum(sn2, sh);
    float meanp = sump * (1.0f / DD);
    float rstdp = rsqrtf(sumsqp * (1.0f / DD) - meanp * meanp + EPS_LN);
    float meann = sumn * (1.0f / DD);
    float rstdn = rsqrtf(sumsqn * (1.0f / DD) - meann * meann + EPS_LN);
    float dp = 0.f, dn = 0.f;
    #pragma unroll
    for (int i = 0; i < 3; i++) {
        int d = t + i * 256;
        float attp = (vp[i] - meanp) * rstdp * g[d] + b[d];
        float attn = (vn[i] - meann) * rstdn * g[d] + b[d];
        float e = sE[(size_t)p * DD + d];
        float a = e - attp + EPS_TRIP;
        float c = e - attn + EPS_TRIP;
        dp += a * a;
        dn += c * c;
    }
    float DP = block_reduce_sum(dp, sh);
    float DN = block_reduce_sum(dn, sh);
    if (t == 0) {
        float hinge = fmaxf(sqrtf(DP) - sqrtf(DN) + 1.0f, 0.f);
        atomicAdd(out, hinge * (1.0f / PP));
    }
}

// ---------------- host launch ----------------
extern "C" void kernel_launch(void* const* d_in, const int* in_sizes, int n_in,
                              void* d_out, int out_size) {
    const float* sent = (const float*)d_in[0];
    const int* sidx = (const int*)d_in[1];
    const int* ss = (const int*)d_in[2];
    const int* ps = (const int*)d_in[3];
    const int* ns = (const int*)d_in[4];
    const float* Wq = (const float*)d_in[5];
    const float* bq = (const float*)d_in[6];
    const float* Wk = (const float*)d_in[7];
    const float* bk = (const float*)d_in[8];
    const float* Wv = (const float*)d_in[9];
    const float* bv = (const float*)d_in[10];
    const float* Wo = (const float*)d_in[11];
    const float* bo = (const float*)d_in[12];
    const float* l1g = (const float*)d_in[13];
    const float* l1b = (const float*)d_in[14];
    const float* l2g = (const float*)d_in[15];
    const float* l2b = (const float*)d_in[16];
    const float* W1 = (const float*)d_in[17];
    const float* b1 = (const float*)d_in[18];
    const float* W2 = (const float*)d_in[19];
    const float* b2 = (const float*)d_in[20];
    float* out = (float*)d_out;

    float *sE, *xb, *qb, *Kb, *Vb, *ao, *hb, *f2;
    bf16 *obf, *hbf, *f1bf, *To, *T2;
    cudaGetSymbolAddress((void**)&sE, g_sE);
    cudaGetSymbolAddress((void**)&xb, g_x);
    cudaGetSymbolAddress((void**)&qb, g_q);
    cudaGetSymbolAddress((void**)&Kb, g_K);
    cudaGetSymbolAddress((void**)&Vb, g_V);
    cudaGetSymbolAddress((void**)&ao, g_ao);
    cudaGetSymbolAddress((void**)&hb, g_h);
    cudaGetSymbolAddress((void**)&f2, g_f2);
    cudaGetSymbolAddress((void**)&obf, g_obf);
    cudaGetSymbolAddress((void**)&hbf, g_hbf);
    cudaGetSymbolAddress((void**)&f1bf, g_f1bf);
    cudaGetSymbolAddress((void**)&To, g_To);
    cudaGetSymbolAddress((void**)&T2, g_T2);

    cudaFuncSetAttribute(tgemm_qkv, cudaFuncAttributeMaxDynamicSharedMemorySize, SMEM_BYTES);
    cudaFuncSetAttribute(tgemm_split<3>, cudaFuncAttributeMaxDynamicSharedMemorySize, SMEM_BYTES);
    cudaFuncSetAttribute(tgemm_split<4>, cudaFuncAttributeMaxDynamicSharedMemorySize, SMEM_BYTES);
    cudaFuncSetAttribute(tgemm_w1, cudaFuncAttributeMaxDynamicSharedMemorySize, SMEM_BYTES);

    // one-time side-stream + events
    static cudaStream_t s2 = nullptr;
    static cudaEvent_t evFork = nullptr, evJoin = nullptr;
    if (s2 == nullptr) {
        cudaStreamCreateWithFlags(&s2, cudaStreamNonBlocking);
        cudaEventCreateWithFlags(&evFork, cudaEventDisableTiming);
        cudaEventCreateWithFlags(&evJoin, cudaEventDisableTiming);
    }

    // PDL launch attribute
    cudaLaunchAttribute pa[1];
    pa[0].id = cudaLaunchAttributeProgrammaticStreamSerialization;
    pa[0].val.programmaticStreamSerializationAllowed = 1;
    auto pdl = [&](dim3 g, dim3 b, size_t sm) {
        cudaLaunchConfig_t c{};
        c.gridDim = g; c.blockDim = b; c.dynamicSmemBytes = sm;
        c.stream = 0; c.attrs = pa; c.numAttrs = 1;
        return c;
    };

    // fork: To/T1/T2 conversion runs concurrently with prep1+QKV+attn
    cudaEventRecord(evFork, 0);
    cudaStreamWaitEvent(s2, evFork, 0);
    prep2_kernel<<<5184, 256, 0, s2>>>(Wo, W1, W2);
    cudaEventRecord(evJoin, s2);

    prep1_kernel<<<1984, 256>>>(Wq, Wk, Wv, sent, sidx, ss, ps, ns, out);

    dim3 gQKV(12, 8, 3);   // 288 blocks, 6 iters
    dim3 gWo(12, 8, 3);    // 288 blocks, 2 iters (split-3)
    dim3 gW1(48, 8, 1);    // 384 blocks, 6 iters
    dim3 gW2(12, 8, 4);    // 384 blocks, 6 iters

    {   // QKV: PDL after prep1
        cudaLaunchConfig_t c = pdl(gQKV, dim3(128), SMEM_BYTES);
        cudaLaunchKernelEx(&c, tgemm_qkv, bq, bk, bv);
    }
    {   // attn: PDL after QKV
        cudaLaunchConfig_t c = pdl(dim3(M2 * HH / 8), dim3(256), 0);
        cudaLaunchKernelEx(&c, attn_kernel,
                           (const float*)qb, (const float*)Kb, (const float*)Vb, obf);
    }

    // join: Wo/W1/W2 need the converted weights; Wo also PDL-overlaps attn's tail
    cudaStreamWaitEvent(0, evJoin, 0);
    {   // Wo: PDL after attn (+ event join from prep2)
        cudaLaunchConfig_t c = pdl(gWo, dim3(128), SMEM_BYTES);
        cudaLaunchKernelEx(&c, tgemm_split<3>,
                           (const bf16*)obf, (const bf16*)To, ao, M2, DD, DD);
    }

    {   // add_ln: PDL after Wo
        cudaLaunchConfig_t c = pdl(dim3(M2), dim3(256), 0);
        cudaLaunchKernelEx(&c, add_ln_kernel,
                           (const float*)xb, (const float*)ao, bo, l1g, l1b, hb, hbf);
    }
    {   // W1: PDL after add_ln
        cudaLaunchConfig_t c = pdl(gW1, dim3(128), SMEM_BYTES);
        cudaLaunchKernelEx(&c, tgemm_w1, b1);
    }
    {   // W2: PDL after W1
        cudaLaunchConfig_t c = pdl(gW2, dim3(128), SMEM_BYTES);
        cudaLaunchKernelEx(&c, tgemm_split<4>,
                           (const bf16*)f1bf, (const bf16*)T2, f2, M2, DFF, DD);
    }
    {   // loss: PDL after W2
        cudaLaunchConfig_t c = pdl(dim3(PP), dim3(256), 0);
        cudaLaunchKernelEx(&c, add_ln_loss_kernel,
                           (const float*)hb, (const float*)f2, b2, l2g, l2b,
                           (const float*)sE, out);
    }
}